// round 16
// baseline (speedup 1.0000x reference)
#include <cuda_runtime.h>
#include <cstdint>
#include <cstddef>

#define TSTEPS 512
#define BATCH  64
#define HID    1024
#define G3     3072
#define MROWS  (TSTEPS * BATCH)   // 32768

// ---- scratch (device globals; no runtime allocation allowed) ----
__device__ float g_gi[(size_t)MROWS * G3];   // 384 MB
__device__ float g_y0[(size_t)MROWS * HID];  // 128 MB
__device__ float g_ha[BATCH * HID];
__device__ float g_hb[BATCH * HID];
// distributed barrier flags: [parity][block] with 128B stride (32 u32)
__device__ unsigned g_flags[2][128 * 32];

// ---- helpers ----
__device__ __forceinline__ uint32_t f2tf(float f) {
    uint32_t u;
    asm("cvt.rna.tf32.f32 %0, %1;" : "=r"(u) : "f"(f));
    return u;
}

__device__ __forceinline__ void mma_tf32(float d[4],
    uint32_t a0, uint32_t a1, uint32_t a2, uint32_t a3,
    uint32_t b0, uint32_t b1)
{
    asm volatile(
        "mma.sync.aligned.m16n8k8.row.col.f32.tf32.tf32.f32 "
        "{%0,%1,%2,%3},{%4,%5,%6,%7},{%8,%9},{%0,%1,%2,%3};"
        : "+f"(d[0]), "+f"(d[1]), "+f"(d[2]), "+f"(d[3])
        : "r"(a0), "r"(a1), "r"(a2), "r"(a3), "r"(b0), "r"(b1));
}

__device__ __forceinline__ float frcp(float x) {
    float r; asm("rcp.approx.f32 %0, %1;" : "=f"(r) : "f"(x)); return r;
}
__device__ __forceinline__ float fex2(float x) {
    float r; asm("ex2.approx.f32 %0, %1;" : "=f"(r) : "f"(x)); return r;
}
__device__ __forceinline__ float fsig(float x) {
    return frcp(1.0f + fex2(-1.4426950408889634f * x));
}
__device__ __forceinline__ float ftanh(float x) {
    return 1.0f - 2.0f * frcp(1.0f + fex2(2.8853900817779268f * x));
}

// ============================================================================
// Big GEMM (unchanged): C = A @ W^T + bias, tf32 mma.sync.
// ============================================================================
#define GBM 128
#define GBN 128
#define GBK 16
#define GSTR 20

__global__ __launch_bounds__(256) void gemm_tn_bias(
    const float* __restrict__ A,
    const float* __restrict__ W,
    const float* __restrict__ bias,
    float* __restrict__ C,
    int K, int N)
{
    __shared__ uint32_t As[2][GBM * GSTR];
    __shared__ uint32_t Bs[2][GBN * GSTR];

    const int t    = threadIdx.x;
    const int bm   = blockIdx.y, bn = blockIdx.x;
    const int warp = t >> 5, lane = t & 31;
    const int wm   = warp >> 1, wn = warp & 1;
    const int g    = lane >> 2, tg = lane & 3;

    const float* Ab = A + (size_t)bm * GBM * K;
    const float* Wb = W + (size_t)bn * GBN * K;

    const int lr = t >> 1;
    const int lq = (t & 1) * 8;

    float acc[2][8][4];
#pragma unroll
    for (int i = 0; i < 2; ++i)
#pragma unroll
        for (int j = 0; j < 8; ++j)
#pragma unroll
            for (int k = 0; k < 4; ++k) acc[i][j][k] = 0.0f;

    float4 ra0, ra1, rw0, rw1;

    ra0 = *(const float4*)(Ab + (size_t)lr * K + lq);
    ra1 = *(const float4*)(Ab + (size_t)lr * K + lq + 4);
    rw0 = *(const float4*)(Wb + (size_t)lr * K + lq);
    rw1 = *(const float4*)(Wb + (size_t)lr * K + lq + 4);
    {
        uint32_t* as = As[0]; uint32_t* bs = Bs[0];
        as[lr * GSTR + lq + 0] = f2tf(ra0.x);
        as[lr * GSTR + lq + 1] = f2tf(ra0.y);
        as[lr * GSTR + lq + 2] = f2tf(ra0.z);
        as[lr * GSTR + lq + 3] = f2tf(ra0.w);
        as[lr * GSTR + lq + 4] = f2tf(ra1.x);
        as[lr * GSTR + lq + 5] = f2tf(ra1.y);
        as[lr * GSTR + lq + 6] = f2tf(ra1.z);
        as[lr * GSTR + lq + 7] = f2tf(ra1.w);
        bs[lr * GSTR + lq + 0] = f2tf(rw0.x);
        bs[lr * GSTR + lq + 1] = f2tf(rw0.y);
        bs[lr * GSTR + lq + 2] = f2tf(rw0.z);
        bs[lr * GSTR + lq + 3] = f2tf(rw0.w);
        bs[lr * GSTR + lq + 4] = f2tf(rw1.x);
        bs[lr * GSTR + lq + 5] = f2tf(rw1.y);
        bs[lr * GSTR + lq + 6] = f2tf(rw1.z);
        bs[lr * GSTR + lq + 7] = f2tf(rw1.w);
    }

    const int NCH = K / GBK;
    for (int c = 0; c < NCH; ++c) {
        __syncthreads();
        const int b = c & 1;
        if (c + 1 < NCH) {
            const int kg = (c + 1) * GBK;
            ra0 = *(const float4*)(Ab + (size_t)lr * K + kg + lq);
            ra1 = *(const float4*)(Ab + (size_t)lr * K + kg + lq + 4);
            rw0 = *(const float4*)(Wb + (size_t)lr * K + kg + lq);
            rw1 = *(const float4*)(Wb + (size_t)lr * K + kg + lq + 4);
        }
#pragma unroll
        for (int ks = 0; ks < 2; ++ks) {
            const int k0 = ks * 8;
            uint32_t af[2][4], bf[8][2];
#pragma unroll
            for (int mt = 0; mt < 2; ++mt) {
                const int rb = wm * 32 + mt * 16;
                af[mt][0] = As[b][(rb + g    ) * GSTR + k0 + tg    ];
                af[mt][1] = As[b][(rb + g + 8) * GSTR + k0 + tg    ];
                af[mt][2] = As[b][(rb + g    ) * GSTR + k0 + tg + 4];
                af[mt][3] = As[b][(rb + g + 8) * GSTR + k0 + tg + 4];
            }
#pragma unroll
            for (int nt = 0; nt < 8; ++nt) {
                const int nb = wn * 64 + nt * 8;
                bf[nt][0] = Bs[b][(nb + g) * GSTR + k0 + tg    ];
                bf[nt][1] = Bs[b][(nb + g) * GSTR + k0 + tg + 4];
            }
#pragma unroll
            for (int mt = 0; mt < 2; ++mt)
#pragma unroll
                for (int nt = 0; nt < 8; ++nt)
                    mma_tf32(acc[mt][nt],
                             af[mt][0], af[mt][1], af[mt][2], af[mt][3],
                             bf[nt][0], bf[nt][1]);
        }
        if (c + 1 < NCH) {
            const int nb2 = (c + 1) & 1;
            uint32_t* as = As[nb2]; uint32_t* bs = Bs[nb2];
            as[lr * GSTR + lq + 0] = f2tf(ra0.x);
            as[lr * GSTR + lq + 1] = f2tf(ra0.y);
            as[lr * GSTR + lq + 2] = f2tf(ra0.z);
            as[lr * GSTR + lq + 3] = f2tf(ra0.w);
            as[lr * GSTR + lq + 4] = f2tf(ra1.x);
            as[lr * GSTR + lq + 5] = f2tf(ra1.y);
            as[lr * GSTR + lq + 6] = f2tf(ra1.z);
            as[lr * GSTR + lq + 7] = f2tf(ra1.w);
            bs[lr * GSTR + lq + 0] = f2tf(rw0.x);
            bs[lr * GSTR + lq + 1] = f2tf(rw0.y);
            bs[lr * GSTR + lq + 2] = f2tf(rw0.z);
            bs[lr * GSTR + lq + 3] = f2tf(rw0.w);
            bs[lr * GSTR + lq + 4] = f2tf(rw1.x);
            bs[lr * GSTR + lq + 5] = f2tf(rw1.y);
            bs[lr * GSTR + lq + 6] = f2tf(rw1.z);
            bs[lr * GSTR + lq + 7] = f2tf(rw1.w);
        }
    }

#pragma unroll
    for (int mt = 0; mt < 2; ++mt) {
        const int row = bm * GBM + wm * 32 + mt * 16 + g;
#pragma unroll
        for (int nt = 0; nt < 8; ++nt) {
            const int col = bn * GBN + wn * 64 + nt * 8 + tg * 2;
            const float b0 = bias[col], b1 = bias[col + 1];
            float2 v0 = make_float2(acc[mt][nt][0] + b0, acc[mt][nt][1] + b1);
            float2 v1 = make_float2(acc[mt][nt][2] + b0, acc[mt][nt][3] + b1);
            *(float2*)(C + (size_t)row * N + col)       = v0;
            *(float2*)(C + (size_t)(row + 8) * N + col) = v1;
        }
    }
}

// ============================================================================
// Persistent recurrence kernel (R14 structure, R15 distributed barrier).
// ============================================================================
#define RBLK 128
#define RTHR 256
#define RCOLS 8
#define WSTR 1028
#define HSTR 36
#define WBUF_U32 (32 * HSTR)
#define WS_U32 (24 * WSTR)
#define RED_OFF (WS_U32 + 8 * 2 * WBUF_U32)
#define RED_U32 (8 * 32 * 7 * 4)
#define RSM_U32 (RED_OFF + RED_U32)

// Distributed sense-counting barrier:
// arrive = one st.release.gpu to this block's 128B-strided flag slot;
// wait   = threads 0..127 each acquire-poll one producer's flag (monotonic >=).
// No single-address atomic contention, no explicit MEMBAR.
__device__ __forceinline__ void grid_bar(int t, int bid) {
    __syncthreads();
    const unsigned tgt = (unsigned)(t >> 1) + 1u;
    const int p = t & 1;
    if (threadIdx.x == 0) {
        asm volatile("st.release.gpu.u32 [%0], %1;"
                     :: "l"(&g_flags[p][bid * 32]), "r"(tgt) : "memory");
    }
    if (threadIdx.x < 128) {
        const unsigned* f = &g_flags[p][threadIdx.x * 32];
        unsigned v;
        do {
            asm volatile("ld.acquire.gpu.u32 %0, [%1];"
                         : "=r"(v) : "l"(f) : "memory");
        } while (v < tgt);
    }
    __syncthreads();
}

__device__ __forceinline__ float2 ldcs2(const float* p) {
    float2 v;
    asm volatile("ld.global.cs.v2.f32 {%0,%1}, [%2];"
                 : "=f"(v.x), "=f"(v.y) : "l"(p));
    return v;
}

__global__ void __launch_bounds__(RTHR, 1) gru_rec(
    const float* __restrict__ gi_base,
    const float* __restrict__ h0,
    const float* __restrict__ w_hh,
    const float* __restrict__ b_hh,
    float* __restrict__ hbuf0,
    float* __restrict__ hbuf1,
    float* __restrict__ y,
    float* __restrict__ hn)
{
    extern __shared__ uint32_t sm[];
    uint32_t* Ws   = sm;
    float4*   red4 = (float4*)(sm + RED_OFF);
    float2*   red2 = (float2*)red4;

    const int tid  = threadIdx.x;
    const int warp = tid >> 5, lane = tid & 31;
    const int g    = lane >> 2, tg = lane & 3;
    const int mg   = warp & 1;
    const int kq   = warp >> 1;
    const int bid  = blockIdx.x;
    const int j0   = bid * RCOLS;

    uint32_t* Hw = sm + WS_U32 + warp * (2 * WBUF_U32);

    // ---- cache w_hh slice (24 rows x 1024) in smem as tf32, once ----
#pragma unroll 4
    for (int j = 0; j < 24; ++j) {
        const int u = tid + j * RTHR;
        const int r = u >> 8;
        const int q = u & 255;
        const int grow = (r >> 3) * HID + j0 + (r & 7);
        float4 v = *(const float4*)(w_hh + (size_t)grow * HID + q * 4);
        uint32_t* dst = Ws + r * WSTR + q * 4;
        dst[0] = f2tf(v.x); dst[1] = f2tf(v.y);
        dst[2] = f2tf(v.z); dst[3] = f2tf(v.w);
    }

    // ---- gate-thread mapping: all 256 threads, one float2 output each ----
    const int qc   = tid & 3;
    const int m    = tid >> 2;
    const int col  = j0 + qc * 2;
    const int mg_o = m >> 5;
    const int mt_o = (m >> 4) & 1;
    const int hi   = (m >> 3) & 1;
    const int g_o  = m & 7;
    const int lane2 = g_o * 4 + qc;

    const float2 bhr = *(const float2*)(b_hh + col);
    const float2 bhz = *(const float2*)(b_hh + HID + col);
    const float2 bhn = *(const float2*)(b_hh + 2 * HID + col);

    float2 gi_r = ldcs2(gi_base + (size_t)m * G3 + col);
    float2 gi_z = ldcs2(gi_base + (size_t)m * G3 + HID + col);
    float2 gi_n = ldcs2(gi_base + (size_t)m * G3 + 2 * HID + col);
    float2 hprev = *(const float2*)(h0 + m * HID + col);

    const int lrow = lane >> 3;
    const int lq8  = lane & 7;

    __syncthreads();

    for (int t = 0; t < TSTEPS; ++t) {
        const float* h_in = (t == 0) ? h0 : ((t & 1) ? hbuf0 : hbuf1);
        float* h_out = (t & 1) ? hbuf1 : hbuf0;

        float acc[2][3][4];
#pragma unroll
        for (int a = 0; a < 2; ++a)
#pragma unroll
            for (int b = 0; b < 3; ++b)
#pragma unroll
                for (int d = 0; d < 4; ++d) acc[a][b][d] = 0.0f;

        const float* hq = h_in + (size_t)(mg * 32 + lrow) * HID + kq * 256 + lq8 * 4;

        float4 ra[8], rb[8];

        // ---- prologue: chunk0 -> buf0; chunk1 -> ra ----
#pragma unroll
        for (int i = 0; i < 8; ++i)
            ra[i] = __ldcg((const float4*)(hq + (size_t)i * 4 * HID));
#pragma unroll
        for (int i = 0; i < 8; ++i) {
            uint4 pv = make_uint4(f2tf(ra[i].x), f2tf(ra[i].y),
                                  f2tf(ra[i].z), f2tf(ra[i].w));
            *(uint4*)(Hw + (lrow + i * 4) * HSTR + lq8 * 4) = pv;
        }
#pragma unroll
        for (int i = 0; i < 8; ++i)
            ra[i] = __ldcg((const float4*)(hq + (size_t)i * 4 * HID + 32));
        __syncwarp();

        // ---- warp-autonomous 2-deep pipeline over 8 chunks ----
#pragma unroll
        for (int c = 0; c < 8; ++c) {
            if (c + 2 < 8) {
                const float* src = hq + (c + 2) * 32;
                if (c & 1) {
#pragma unroll
                    for (int i = 0; i < 8; ++i)
                        ra[i] = __ldcg((const float4*)(src + (size_t)i * 4 * HID));
                } else {
#pragma unroll
                    for (int i = 0; i < 8; ++i)
                        rb[i] = __ldcg((const float4*)(src + (size_t)i * 4 * HID));
                }
            }
            const uint32_t* Hc = Hw + (c & 1) * WBUF_U32;
#pragma unroll
            for (int ks = 0; ks < 4; ++ks) {
                const int k0 = ks * 8;
                uint32_t a0[4], a1[4];
                a0[0] = Hc[(g     ) * HSTR + k0 + tg    ];
                a0[1] = Hc[(g +  8) * HSTR + k0 + tg    ];
                a0[2] = Hc[(g     ) * HSTR + k0 + tg + 4];
                a0[3] = Hc[(g +  8) * HSTR + k0 + tg + 4];
                a1[0] = Hc[(g + 16) * HSTR + k0 + tg    ];
                a1[1] = Hc[(g + 24) * HSTR + k0 + tg    ];
                a1[2] = Hc[(g + 16) * HSTR + k0 + tg + 4];
                a1[3] = Hc[(g + 24) * HSTR + k0 + tg + 4];
                const int wk = kq * 256 + c * 32 + k0 + tg;
#pragma unroll
                for (int nt = 0; nt < 3; ++nt) {
                    const uint32_t b0 = Ws[(nt * 8 + g) * WSTR + wk    ];
                    const uint32_t b1 = Ws[(nt * 8 + g) * WSTR + wk + 4];
                    mma_tf32(acc[0][nt], a0[0], a0[1], a0[2], a0[3], b0, b1);
                    mma_tf32(acc[1][nt], a1[0], a1[1], a1[2], a1[3], b0, b1);
                }
            }
            if (c + 1 < 8) {
                uint32_t* dst = Hw + ((c + 1) & 1) * WBUF_U32;
                if (c & 1) {
#pragma unroll
                    for (int i = 0; i < 8; ++i) {
                        uint4 pv = make_uint4(f2tf(rb[i].x), f2tf(rb[i].y),
                                              f2tf(rb[i].z), f2tf(rb[i].w));
                        *(uint4*)(dst + (lrow + i * 4) * HSTR + lq8 * 4) = pv;
                    }
                } else {
#pragma unroll
                    for (int i = 0; i < 8; ++i) {
                        uint4 pv = make_uint4(f2tf(ra[i].x), f2tf(ra[i].y),
                                              f2tf(ra[i].z), f2tf(ra[i].w));
                        *(uint4*)(dst + (lrow + i * 4) * HSTR + lq8 * 4) = pv;
                    }
                }
                __syncwarp();
            }
        }

        // ---- write k-quarter partials (warp-private region) ----
        {
            const int base = ((kq * 2 + mg) * 32 + lane) * 7;
#pragma unroll
            for (int mt = 0; mt < 2; ++mt)
#pragma unroll
                for (int nt = 0; nt < 3; ++nt)
                    red4[base + mt * 3 + nt] =
                        make_float4(acc[mt][nt][0], acc[mt][nt][1],
                                    acc[mt][nt][2], acc[mt][nt][3]);
        }
        __syncthreads();

        // ---- gather + gates: all 256 threads, one float2 each ----
        {
            float2 s[3];
#pragma unroll
            for (int nt = 0; nt < 3; ++nt)
                s[nt] = red2[((mg_o * 32 + lane2) * 7 + mt_o * 3 + nt) * 2 + hi];
#pragma unroll
            for (int q = 1; q < 4; ++q)
#pragma unroll
                for (int nt = 0; nt < 3; ++nt) {
                    float2 p = red2[(((q * 2 + mg_o) * 32 + lane2) * 7
                                     + mt_o * 3 + nt) * 2 + hi];
                    s[nt].x += p.x; s[nt].y += p.y;
                }

            const float rx = fsig(gi_r.x + s[0].x + bhr.x);
            const float ry = fsig(gi_r.y + s[0].y + bhr.y);
            const float zx = fsig(gi_z.x + s[1].x + bhz.x);
            const float zy = fsig(gi_z.y + s[1].y + bhz.y);
            const float nx = ftanh(gi_n.x + rx * (s[2].x + bhn.x));
            const float ny = ftanh(gi_n.y + ry * (s[2].y + bhn.y));

            float2 hv = make_float2((1.0f - zx) * nx + zx * hprev.x,
                                    (1.0f - zy) * ny + zy * hprev.y);
            hprev = hv;

            float* y_t = y + (size_t)t * BATCH * HID;
            *(float2*)(h_out + m * HID + col) = hv;
            *(float2*)(y_t + m * HID + col)   = hv;
            if (t == TSTEPS - 1)
                *(float2*)(hn + m * HID + col) = hv;

            if (t + 1 < TSTEPS) {
                const float* gim = gi_base + (size_t)(t + 1) * BATCH * G3
                                 + (size_t)m * G3;
                gi_r = ldcs2(gim + col);
                gi_z = ldcs2(gim + HID + col);
                gi_n = ldcs2(gim + 2 * HID + col);
            }
        }

        grid_bar(t, bid);
    }
}

__global__ void bar_reset() {
    // 256 threads clear all 2*128 flag slots
    const int i = threadIdx.x;
    if (i < 128) {
        g_flags[0][i * 32] = 0u;
        g_flags[1][i * 32] = 0u;
    }
}

// ============================================================================
// Launcher: 6-node graph.
// ============================================================================
extern "C" void kernel_launch(void* const* d_in, const int* in_sizes, int n_in,
                              void* d_out, int out_size)
{
    const float* x      = (const float*)d_in[0];
    const float* hx     = (const float*)d_in[1];
    const float* w_ih_0 = (const float*)d_in[2];
    const float* w_hh_0 = (const float*)d_in[3];
    const float* b_ih_0 = (const float*)d_in[4];
    const float* b_hh_0 = (const float*)d_in[5];
    const float* w_ih_1 = (const float*)d_in[6];
    const float* w_hh_1 = (const float*)d_in[7];
    const float* b_ih_1 = (const float*)d_in[8];
    const float* b_hh_1 = (const float*)d_in[9];

    float* out = (float*)d_out;
    float* hn0 = out + (size_t)MROWS * HID;
    float* hn1 = hn0 + (size_t)BATCH * HID;

    float *gi, *y0, *ha, *hb;
    cudaGetSymbolAddress((void**)&gi, g_gi);
    cudaGetSymbolAddress((void**)&y0, g_y0);
    cudaGetSymbolAddress((void**)&ha, g_ha);
    cudaGetSymbolAddress((void**)&hb, g_hb);

    cudaFuncSetAttribute(gru_rec, cudaFuncAttributeMaxDynamicSharedMemorySize,
                         RSM_U32 * 4);

    dim3 ggrid(G3 / GBN, MROWS / GBM);  // (24, 256)

    // ---- layer 0 ----
    gemm_tn_bias<<<ggrid, 256>>>(x, w_ih_0, b_ih_0, gi, HID, G3);
    gru_rec<<<RBLK, RTHR, RSM_U32 * 4>>>(gi, hx, w_hh_0, b_hh_0,
                                         ha, hb, y0, hn0);
    bar_reset<<<1, 256>>>();

    // ---- layer 1 ----
    gemm_tn_bias<<<ggrid, 256>>>(y0, w_ih_1, b_ih_1, gi, HID, G3);
    gru_rec<<<RBLK, RTHR, RSM_U32 * 4>>>(gi, hx + (size_t)BATCH * HID,
                                         w_hh_1, b_hh_1,
                                         ha, hb, out, hn1);
    bar_reset<<<1, 256>>>();

    (void)in_sizes; (void)n_in; (void)out_size;
}